// round 12
// baseline (speedup 1.0000x reference)
#include <cuda_runtime.h>
#include <cuda_bf16.h>
#include <math.h>
#include <stdint.h>

// ---------------------------------------------------------------------------
// Problem constants
// ---------------------------------------------------------------------------
#define BWIN    2048
#define N_TOK   49
#define C_DIM   512
#define N_HEADS 16
#define HD      32
#define QKV_N   1536
#define M_ROWS  (BWIN * N_TOK)     // 100352 = 784 * 128
#define NN      (N_TOK * N_TOK)    // 2401
#define NWMASK  64

// ---------------------------------------------------------------------------
// Scratch (static device globals)
// ---------------------------------------------------------------------------
__device__ float g_qkv[(size_t)M_ROWS * QKV_N];          // fp32 qkv
__device__ __nv_bfloat16 g_xh[(size_t)M_ROWS * C_DIM];   // x split hi
__device__ __nv_bfloat16 g_xl[(size_t)M_ROWS * C_DIM];   // x split lo
__device__ __nv_bfloat16 g_aoh[(size_t)M_ROWS * C_DIM];  // attn out split hi
__device__ __nv_bfloat16 g_aol[(size_t)M_ROWS * C_DIM];  // attn out split lo
__device__ __nv_bfloat16 g_qwh[C_DIM * QKV_N];
__device__ __nv_bfloat16 g_qwl[C_DIM * QKV_N];
__device__ __nv_bfloat16 g_pwh[C_DIM * C_DIM];
__device__ __nv_bfloat16 g_pwl[C_DIM * C_DIM];
__device__ float g_pb [N_HEADS * NN];
__device__ float g_qkvbias[QKV_N];

// ---------------------------------------------------------------------------
// Helpers
// ---------------------------------------------------------------------------
__device__ __forceinline__ uint32_t pack2(__nv_bfloat16 a, __nv_bfloat16 b) {
    __nv_bfloat162 v; v.x = a; v.y = b;
    return *(uint32_t*)&v;
}
__device__ __forceinline__ void split1(float v, __nv_bfloat16& h, __nv_bfloat16& l) {
    h = __float2bfloat16(v);
    l = __float2bfloat16(v - __bfloat162float(h));
}

__device__ __forceinline__ void mma_bf16(float d[4],
                                         const uint32_t a[4],
                                         const uint32_t b[2]) {
    asm volatile(
        "mma.sync.aligned.m16n8k16.row.col.f32.bf16.bf16.f32 "
        "{%0,%1,%2,%3}, {%4,%5,%6,%7}, {%8,%9}, {%0,%1,%2,%3};\n"
        : "+f"(d[0]), "+f"(d[1]), "+f"(d[2]), "+f"(d[3])
        : "r"(a[0]), "r"(a[1]), "r"(a[2]), "r"(a[3]), "r"(b[0]), "r"(b[1]));
}
__device__ __forceinline__ void ldsm_x4(uint32_t r[4], uint32_t addr) {
    asm volatile("ldmatrix.sync.aligned.m8n8.x4.shared.b16 {%0,%1,%2,%3}, [%4];\n"
                 : "=r"(r[0]), "=r"(r[1]), "=r"(r[2]), "=r"(r[3]) : "r"(addr));
}
__device__ __forceinline__ void ldsm_x2t(uint32_t r[2], uint32_t addr) {
    asm volatile("ldmatrix.sync.aligned.m8n8.x2.trans.shared.b16 {%0,%1}, [%2];\n"
                 : "=r"(r[0]), "=r"(r[1]) : "r"(addr));
}
__device__ __forceinline__ void cp16(uint32_t dst, const void* src) {
    asm volatile("cp.async.cg.shared.global [%0], [%1], 16;\n" :: "r"(dst), "l"(src));
}
__device__ __forceinline__ void cp_commit() { asm volatile("cp.async.commit_group;\n"); }
__device__ __forceinline__ void cp_wait1()  { asm volatile("cp.async.wait_group 1;\n" ::: "memory"); }

// ---------------------------------------------------------------------------
// Split kernel: fp32 -> bf16 hi/lo (vectorized x4)
// ---------------------------------------------------------------------------
__global__ void split_kernel(const float* __restrict__ src,
                             __nv_bfloat16* __restrict__ dh,
                             __nv_bfloat16* __restrict__ dl, int n4) {
    int i = blockIdx.x * blockDim.x + threadIdx.x;
    if (i >= n4) return;
    float4 v = ((const float4*)src)[i];
    __nv_bfloat16 hx, lx, hy, ly, hz, lz, hw, lw;
    split1(v.x, hx, lx); split1(v.y, hy, ly);
    split1(v.z, hz, lz); split1(v.w, hw, lw);
    uint2 ph, pl;
    ph.x = pack2(hx, hy); ph.y = pack2(hz, hw);
    pl.x = pack2(lx, ly); pl.y = pack2(lz, lw);
    ((uint2*)dh)[i] = ph;
    ((uint2*)dl)[i] = pl;
}

// ---------------------------------------------------------------------------
// Kernel 1: RPE table MLP + bias gather + qkv bias vector
// ---------------------------------------------------------------------------
__device__ __forceinline__ float coord_feat(int x) {
    float xs = (float)x * (8.0f / 121.0f);
    float v = log1pf(fabsf(xs)) * 0.48089834696298783f; // 1/ln(8)
    return copysignf(v, xs);
}

__global__ void setup_kernel(const float* __restrict__ rpe_w1,
                             const float* __restrict__ rpe_b1,
                             const float* __restrict__ rpe_w2,
                             const float* __restrict__ q_bias,
                             const float* __restrict__ v_bias) {
    __shared__ float sbt[169 * N_HEADS];
    const int tid = threadIdx.x; // 256 threads

    if (tid < 169) {
        int a = tid / 13, b = tid % 13;
        float c0 = coord_feat(b - 6);
        float c1 = coord_feat(a - 6);
        float acc[N_HEADS];
        #pragma unroll
        for (int t = 0; t < N_HEADS; t++) acc[t] = 0.f;
        for (int j = 0; j < 512; j++) {
            float h1 = fmaf(c0, rpe_w1[j], fmaf(c1, rpe_w1[512 + j], rpe_b1[j]));
            h1 = fmaxf(h1, 0.f);
            const float* w2 = rpe_w2 + j * N_HEADS;
            #pragma unroll
            for (int t = 0; t < N_HEADS; t++) acc[t] = fmaf(h1, w2[t], acc[t]);
        }
        #pragma unroll
        for (int t = 0; t < N_HEADS; t++) sbt[tid * N_HEADS + t] = acc[t];
    }

    for (int c = tid; c < QKV_N; c += 256) {
        float v = 0.f;
        if (c < 512)        v = q_bias[c];
        else if (c >= 1024) v = v_bias[c - 1024];
        g_qkvbias[c] = v;
    }
    __syncthreads();

    for (int idx = tid; idx < N_HEADS * NN; idx += 256) {
        int h   = idx / NN;
        int rem = idx % NN;
        int n = rem / N_TOK, m = rem % N_TOK;
        int di = (n / 7) - (m / 7);
        int dj = (n % 7) - (m % 7);
        int r = (dj + 6) * 13 + (di + 6);
        float bt = sbt[r * N_HEADS + h];
        g_pb[idx] = 16.f / (1.f + expf(-bt));
    }
}

// ---------------------------------------------------------------------------
// Pipelined split-bf16 tensor-core GEMM, v3: 128 threads = 4 warps,
// warp tile 64x64, BK=32, THREE-stage cp.async ring (2 iters of latency
// hiding) and ONE __syncthreads per iteration.
// ---------------------------------------------------------------------------
#define SA_STR 40
#define SB_STR 136
#define ASIZE (128 * SA_STR)   // 5120 elems per stage
#define BSIZE (32 * SB_STR)    // 4352 elems per stage
#define STAGES 3
#define SMEM_BYTES (STAGES * (2 * ASIZE + 2 * BSIZE) * 2)  // 113664 B

__device__ __forceinline__ void gemm_issue(
    int it, int buf, int iters, int tid,
    const __nv_bfloat16* Ah, const __nv_bfloat16* Al,
    const __nv_bfloat16* Bh, const __nv_bfloat16* Bl,
    size_t Abase, int nblk, int N, int K,
    uint32_t sAh32, uint32_t sAl32, uint32_t sBh32, uint32_t sBl32)
{
    if (it < iters) {
        const int k0 = it * 32;
        const uint32_t aoff = (uint32_t)buf * (ASIZE * 2);
        const uint32_t boff = (uint32_t)buf * (BSIZE * 2);
        // A tile: 128 rows x 32 k, hi+lo
        #pragma unroll
        for (int p = 0; p < 4; p++) {
            int c = tid + p * 128;
            int row = c >> 2, seg = (c & 3) * 8;
            size_t go = Abase + (size_t)row * K + k0 + seg;
            uint32_t ds = (uint32_t)(row * SA_STR + seg) * 2;
            cp16(sAh32 + aoff + ds, Ah + go);
            cp16(sAl32 + aoff + ds, Al + go);
        }
        // B tile: 32 rows x 128 n, hi+lo
        #pragma unroll
        for (int p = 0; p < 4; p++) {
            int c = tid + p * 128;
            int row = c >> 4, seg = (c & 15) * 8;
            size_t go = (size_t)(k0 + row) * N + nblk + seg;
            uint32_t ds = (uint32_t)(row * SB_STR + seg) * 2;
            cp16(sBh32 + boff + ds, Bh + go);
            cp16(sBl32 + boff + ds, Bl + go);
        }
    }
    cp_commit();   // uniform group count even past the end
}

__device__ __forceinline__ void gemm_core(
    const __nv_bfloat16* __restrict__ Ah, const __nv_bfloat16* __restrict__ Al,
    const __nv_bfloat16* __restrict__ Bh, const __nv_bfloat16* __restrict__ Bl,
    const float* __restrict__ bias, float* __restrict__ C, int N, int K)
{
    extern __shared__ __nv_bfloat16 smem[];
    __nv_bfloat16* sAh = smem;
    __nv_bfloat16* sAl = sAh + STAGES * ASIZE;
    __nv_bfloat16* sBh = sAl + STAGES * ASIZE;
    __nv_bfloat16* sBl = sBh + STAGES * BSIZE;

    const int tid  = threadIdx.x;          // 128 threads
    const int bm   = blockIdx.y, bn = blockIdx.x;
    const int lane = tid & 31;
    const int w    = tid >> 5;              // 0..3
    const int wm   = (w >> 1) * 64;         // 0 or 64
    const int wn   = (w & 1) * 64;          // 0 or 64
    const int l15  = lane & 15;
    const int lhi8 = (lane >> 4) * 8;

    const size_t Abase = (size_t)bm * 128 * K;
    const int nblk = bn * 128;

    const uint32_t sAh32 = (uint32_t)__cvta_generic_to_shared(sAh);
    const uint32_t sAl32 = (uint32_t)__cvta_generic_to_shared(sAl);
    const uint32_t sBh32 = (uint32_t)__cvta_generic_to_shared(sBh);
    const uint32_t sBl32 = (uint32_t)__cvta_generic_to_shared(sBl);

    float acc[4][8][4];
    #pragma unroll
    for (int mi = 0; mi < 4; mi++)
        #pragma unroll
        for (int ni = 0; ni < 8; ni++)
            #pragma unroll
            for (int r = 0; r < 4; r++) acc[mi][ni][r] = 0.f;

    const int iters = K / 32;
    // prologue: stages 0 and 1
    gemm_issue(0, 0, iters, tid, Ah, Al, Bh, Bl, Abase, nblk, N, K, sAh32, sAl32, sBh32, sBl32);
    gemm_issue(1, 1, iters, tid, Ah, Al, Bh, Bl, Abase, nblk, N, K, sAh32, sAl32, sBh32, sBl32);

    int buf = 0, nbuf = 2;   // buf = it % 3; nbuf = (it+2) % 3
    for (int it = 0; it < iters; it++) {
        cp_wait1();          // group(it) complete (<=1 outstanding)
        __syncthreads();     // make stage visible block-wide; fences last iter's reads

        // issue loads for it+2 into slot (it+2)%3 (last read in iter it-1)
        gemm_issue(it + 2, nbuf, iters, tid, Ah, Al, Bh, Bl, Abase, nblk, N, K,
                   sAh32, sAl32, sBh32, sBl32);

        const uint32_t aoff = (uint32_t)buf * (ASIZE * 2);
        const uint32_t boff = (uint32_t)buf * (BSIZE * 2);

        #pragma unroll
        for (int ks = 0; ks < 32; ks += 16) {
            uint32_t bh[8][2], bl[8][2];
            #pragma unroll
            for (int ni = 0; ni < 8; ni++) {
                uint32_t ds = (uint32_t)((ks + l15) * SB_STR + wn + ni * 8) * 2;
                ldsm_x2t(bh[ni], sBh32 + boff + ds);
                ldsm_x2t(bl[ni], sBl32 + boff + ds);
            }
            #pragma unroll
            for (int mi = 0; mi < 4; mi++) {
                uint32_t ds = (uint32_t)((wm + mi * 16 + l15) * SA_STR + ks + lhi8) * 2;
                uint32_t ah[4], al[4];
                ldsm_x4(ah, sAh32 + aoff + ds);
                ldsm_x4(al, sAl32 + aoff + ds);
                #pragma unroll
                for (int ni = 0; ni < 8; ni++) {
                    mma_bf16(acc[mi][ni], ah, bh[ni]);
                    mma_bf16(acc[mi][ni], ah, bl[ni]);
                    mma_bf16(acc[mi][ni], al, bh[ni]);
                }
            }
        }
        buf  = (buf == 2)  ? 0 : buf + 1;
        nbuf = (nbuf == 2) ? 0 : nbuf + 1;
    }

    const int g  = lane >> 2;
    const int t2 = (lane & 3) * 2;
    #pragma unroll
    for (int mi = 0; mi < 4; mi++) {
        int row = bm * 128 + wm + mi * 16 + g;
        #pragma unroll
        for (int ni = 0; ni < 8; ni++) {
            int col = bn * 128 + wn + ni * 8 + t2;
            float b0 = bias[col], b1 = bias[col + 1];
            float2 o0 = make_float2(acc[mi][ni][0] + b0, acc[mi][ni][1] + b1);
            float2 o1 = make_float2(acc[mi][ni][2] + b0, acc[mi][ni][3] + b1);
            *(float2*)(C + (size_t)row * N + col)       = o0;
            *(float2*)(C + (size_t)(row + 8) * N + col) = o1;
        }
    }
}

__global__ void __launch_bounds__(128, 2)
qkv_gemm_kernel() {
    gemm_core(g_xh, g_xl, g_qwh, g_qwl, g_qkvbias, g_qkv, QKV_N, C_DIM);
}

__global__ void __launch_bounds__(128, 2)
proj_gemm_kernel(const float* __restrict__ proj_b, float* __restrict__ out) {
    gemm_core(g_aoh, g_aol, g_pwh, g_pwl, proj_b, out, C_DIM, C_DIM);
}

// ---------------------------------------------------------------------------
// Kernel 3: tensor-core attention per (window, head) — unchanged (validated R10)
// ---------------------------------------------------------------------------
#define ATT_QH  0
#define ATT_QL  5120
#define ATT_KTH 10240
#define ATT_KTL 14848
#define ATT_VH  19456
#define ATT_VL  24576
#define ATT_SS  29696
#define ATT_TOT (29696 + 64 * 66 * 4)   // 46592 B
#define ATT_PH  0
#define ATT_PL  9216

__global__ void __launch_bounds__(256, 2)
attn_kernel(const float* __restrict__ mask, const float* __restrict__ logit_scale) {
    const int b = blockIdx.x >> 4;
    const int h = blockIdx.x & 15;
    const int tid  = threadIdx.x;
    const int lane = tid & 31;
    const int w    = tid >> 5;

    __shared__ __align__(16) char sm[ATT_TOT];
    __nv_bfloat16* sQh  = (__nv_bfloat16*)(sm + ATT_QH);
    __nv_bfloat16* sQl  = (__nv_bfloat16*)(sm + ATT_QL);
    __nv_bfloat16* sKth = (__nv_bfloat16*)(sm + ATT_KTH);
    __nv_bfloat16* sKtl = (__nv_bfloat16*)(sm + ATT_KTL);
    __nv_bfloat16* sVh  = (__nv_bfloat16*)(sm + ATT_VH);
    __nv_bfloat16* sVl  = (__nv_bfloat16*)(sm + ATT_VL);
    __nv_bfloat16* sPh  = (__nv_bfloat16*)(sm + ATT_PH);
    __nv_bfloat16* sPl  = (__nv_bfloat16*)(sm + ATT_PL);
    float* sS = (float*)(sm + ATT_SS);
    const uint32_t smb = (uint32_t)__cvta_generic_to_shared(sm);

    // ---- Phase 1: load q,k fp32 into staging; v split directly ----
    const float* base = g_qkv + (size_t)b * N_TOK * QKV_N + h * HD;
    #pragma unroll
    for (int p = 0; p < 8; p++) {
        int idx = tid + p * 256;
        int r = idx >> 5, d = idx & 31;
        float qv = 0.f, kv = 0.f, vv = 0.f;
        if (r < N_TOK) {
            const float* pp = base + (size_t)r * QKV_N + d;
            qv = pp[0]; kv = pp[512]; vv = pp[1024];
        }
        sS[r * 66 + d]      = qv;
        sS[r * 66 + 32 + d] = kv;
        __nv_bfloat16 vh, vl;
        split1(vv, vh, vl);
        sVh[r * 40 + d] = vh;
        sVl[r * 40 + d] = vl;
    }
    __syncthreads();

    // ---- Phase 2: normalize rows (4 threads/row, uniform), split Q / K^T ----
    {
        const int r  = tid >> 2;
        const int qd = (tid & 3) * 8;
        float qv[8], kv[8];
        float sq = 0.f, sk = 0.f;
        #pragma unroll
        for (int j = 0; j < 8; j++) {
            qv[j] = sS[r * 66 + qd + j];
            kv[j] = sS[r * 66 + 32 + qd + j];
            sq = fmaf(qv[j], qv[j], sq);
            sk = fmaf(kv[j], kv[j], sk);
        }
        sq += __shfl_xor_sync(0xffffffff, sq, 1);
        sq += __shfl_xor_sync(0xffffffff, sq, 2);
        sk += __shfl_xor_sync(0xffffffff, sk, 1);
        sk += __shfl_xor_sync(0xffffffff, sk, 2);
        float hs  = __expf(fminf(logit_scale[h], 4.605170185988091f));
        float qsc = rsqrtf(fmaxf(sq, 1e-12f)) * hs;
        float ksc = rsqrtf(fmaxf(sk, 1e-12f));
        #pragma unroll
        for (int j = 0; j < 8; j += 2) {
            __nv_bfloat16 h0, l0, h1, l1;
            split1(qv[j] * qsc, h0, l0);
            split1(qv[j + 1] * qsc, h1, l1);
            *(uint32_t*)&sQh[r * 40 + qd + j] = pack2(h0, h1);
            *(uint32_t*)&sQl[r * 40 + qd + j] = pack2(l0, l1);
        }
        #pragma unroll
        for (int j = 0; j < 8; j++) {
            __nv_bfloat16 kh, kl;
            split1(kv[j] * ksc, kh, kl);
            sKth[(qd + j) * 72 + r] = kh;
            sKtl[(qd + j) * 72 + r] = kl;
        }
    }
    __syncthreads();

    // ---- Phase 3: S = Qn @ Kn^T via 3-term split-bf16 MMA ----
    {
        const int m0  = (w & 3) * 16;
        const int n0  = (w >> 2) * 32;
        const int l15 = lane & 15;
        const int lhi8 = (lane >> 4) * 8;
        float acc[4][4];
        #pragma unroll
        for (int ni = 0; ni < 4; ni++)
            #pragma unroll
            for (int r = 0; r < 4; r++) acc[ni][r] = 0.f;

        #pragma unroll
        for (int ks = 0; ks < 32; ks += 16) {
            uint32_t ah[4], al[4];
            uint32_t dsA = (uint32_t)(ATT_QH) + (uint32_t)((m0 + l15) * 40 + ks + lhi8) * 2;
            ldsm_x4(ah, smb + dsA);
            ldsm_x4(al, smb + dsA + (ATT_QL - ATT_QH));
            #pragma unroll
            for (int ni = 0; ni < 4; ni++) {
                uint32_t bh[2], bl[2];
                uint32_t dsB = (uint32_t)(ATT_KTH) + (uint32_t)((ks + l15) * 72 + n0 + ni * 8) * 2;
                ldsm_x2t(bh, smb + dsB);
                ldsm_x2t(bl, smb + dsB + (ATT_KTL - ATT_KTH));
                mma_bf16(acc[ni], ah, bh);
                mma_bf16(acc[ni], ah, bl);
                mma_bf16(acc[ni], al, bh);
            }
        }
        const int g  = lane >> 2;
        const int t2 = (lane & 3) * 2;
        #pragma unroll
        for (int ni = 0; ni < 4; ni++) {
            int c = n0 + ni * 8 + t2;
            *(float2*)&sS[(m0 + g) * 66 + c]     = make_float2(acc[ni][0], acc[ni][1]);
            *(float2*)&sS[(m0 + 8 + g) * 66 + c] = make_float2(acc[ni][2], acc[ni][3]);
        }
    }
    __syncthreads();

    // ---- Phase 4: softmax (4 threads/row), UNIFORM across all 64 rows ----
    {
        const int r  = tid >> 2;
        const int c0 = (tid & 3) * 16;
        const int rr = (r < N_TOK) ? r : 0;
        const int ww = b & (NWMASK - 1);
        const float* pbr = g_pb + h * NN + rr * N_TOK;
        const float* mr  = mask + (size_t)ww * NN + rr * N_TOK;
        float vals[16];
        float mx = -1e30f;
        #pragma unroll
        for (int i = 0; i < 16; i++) {
            int m = c0 + i;
            float v = -1e30f;
            if (m < N_TOK) v = sS[r * 66 + m] + pbr[m] + mr[m];
            vals[i] = v;
            mx = fmaxf(mx, v);
        }
        mx = fmaxf(mx, __shfl_xor_sync(0xffffffff, mx, 1));
        mx = fmaxf(mx, __shfl_xor_sync(0xffffffff, mx, 2));
        float sum = 0.f;
        #pragma unroll
        for (int i = 0; i < 16; i++) {
            float e = (c0 + i < N_TOK) ? __expf(vals[i] - mx) : 0.f;
            vals[i] = e;
            sum += e;
        }
        sum += __shfl_xor_sync(0xffffffff, sum, 1);
        sum += __shfl_xor_sync(0xffffffff, sum, 2);
        float inv = 1.f / sum;
        #pragma unroll
        for (int i = 0; i < 16; i += 2) {
            __nv_bfloat16 h0, l0, h1, l1;
            split1(vals[i] * inv, h0, l0);
            split1(vals[i + 1] * inv, h1, l1);
            *(uint32_t*)&sPh[r * 72 + c0 + i] = pack2(h0, h1);
            *(uint32_t*)&sPl[r * 72 + c0 + i] = pack2(l0, l1);
        }
    }
    __syncthreads();

    // ---- Phase 5: O = P @ V via 3-term split-bf16 MMA; split-store output ----
    {
        const int m0  = (w & 3) * 16;
        const int n0  = (w >> 2) * 16;
        const int l15 = lane & 15;
        const int lhi8 = (lane >> 4) * 8;
        float acc[2][4];
        #pragma unroll
        for (int ni = 0; ni < 2; ni++)
            #pragma unroll
            for (int r = 0; r < 4; r++) acc[ni][r] = 0.f;

        #pragma unroll
        for (int ks = 0; ks < 64; ks += 16) {
            uint32_t ah[4], al[4];
            uint32_t dsA = (uint32_t)(ATT_PH) + (uint32_t)((m0 + l15) * 72 + ks + lhi8) * 2;
            ldsm_x4(ah, smb + dsA);
            ldsm_x4(al, smb + dsA + (ATT_PL - ATT_PH));
            #pragma unroll
            for (int ni = 0; ni < 2; ni++) {
                uint32_t bh[2], bl[2];
                uint32_t dsB = (uint32_t)(ATT_VH) + (uint32_t)((ks + l15) * 40 + n0 + ni * 8) * 2;
                ldsm_x2t(bh, smb + dsB);
                ldsm_x2t(bl, smb + dsB + (ATT_VL - ATT_VH));
                mma_bf16(acc[ni], ah, bh);
                mma_bf16(acc[ni], ah, bl);
                mma_bf16(acc[ni], al, bh);
            }
        }
        const int g  = lane >> 2;
        const int t2 = (lane & 3) * 2;
        #pragma unroll
        for (int ni = 0; ni < 2; ni++) {
            int col  = h * HD + n0 + ni * 8 + t2;
            int row0 = m0 + g, row1 = m0 + 8 + g;
            if (row0 < N_TOK) {
                size_t o = ((size_t)b * N_TOK + row0) * C_DIM + col;
                __nv_bfloat16 h0, l0, h1, l1;
                split1(acc[ni][0], h0, l0);
                split1(acc[ni][1], h1, l1);
                *(uint32_t*)(g_aoh + o) = pack2(h0, h1);
                *(uint32_t*)(g_aol + o) = pack2(l0, l1);
            }
            if (row1 < N_TOK) {
                size_t o = ((size_t)b * N_TOK + row1) * C_DIM + col;
                __nv_bfloat16 h0, l0, h1, l1;
                split1(acc[ni][2], h0, l0);
                split1(acc[ni][3], h1, l1);
                *(uint32_t*)(g_aoh + o) = pack2(h0, h1);
                *(uint32_t*)(g_aol + o) = pack2(l0, l1);
            }
        }
    }
}

// ---------------------------------------------------------------------------
// Launch
// ---------------------------------------------------------------------------
extern "C" void kernel_launch(void* const* d_in, const int* in_sizes, int n_in,
                              void* d_out, int out_size) {
    const float* x           = (const float*)d_in[0];
    const float* mask        = (const float*)d_in[1];
    const float* qkv_w       = (const float*)d_in[2];
    const float* q_bias      = (const float*)d_in[3];
    const float* v_bias      = (const float*)d_in[4];
    const float* logit_scale = (const float*)d_in[5];
    const float* rpe_w1      = (const float*)d_in[6];
    const float* rpe_b1      = (const float*)d_in[7];
    const float* rpe_w2      = (const float*)d_in[8];
    const float* proj_w      = (const float*)d_in[9];
    const float* proj_b      = (const float*)d_in[10];
    float* out = (float*)d_out;

    cudaFuncSetAttribute(qkv_gemm_kernel,
                         cudaFuncAttributeMaxDynamicSharedMemorySize, SMEM_BYTES);
    cudaFuncSetAttribute(proj_gemm_kernel,
                         cudaFuncAttributeMaxDynamicSharedMemorySize, SMEM_BYTES);

    __nv_bfloat16 *xh, *xl, *qwh, *qwl, *pwh, *pwl;
    cudaGetSymbolAddress((void**)&xh,  g_xh);
    cudaGetSymbolAddress((void**)&xl,  g_xl);
    cudaGetSymbolAddress((void**)&qwh, g_qwh);
    cudaGetSymbolAddress((void**)&qwl, g_qwl);
    cudaGetSymbolAddress((void**)&pwh, g_pwh);
    cudaGetSymbolAddress((void**)&pwl, g_pwl);

    setup_kernel<<<1, 256>>>(rpe_w1, rpe_b1, rpe_w2, q_bias, v_bias);

    {
        int n4 = M_ROWS * C_DIM / 4;
        split_kernel<<<(n4 + 255) / 256, 256>>>(x, xh, xl, n4);
    }
    {
        int n4 = C_DIM * QKV_N / 4;
        split_kernel<<<(n4 + 255) / 256, 256>>>(qkv_w, qwh, qwl, n4);
    }
    {
        int n4 = C_DIM * C_DIM / 4;
        split_kernel<<<(n4 + 255) / 256, 256>>>(proj_w, pwh, pwl, n4);
    }

    // QKV: [100352,512] @ [512,1536], 128-thread blocks
    qkv_gemm_kernel<<<dim3(QKV_N / 128, M_ROWS / 128), 128, SMEM_BYTES>>>();

    attn_kernel<<<BWIN * N_HEADS, 256>>>(mask, logit_scale);

    // proj: [100352,512] @ [512,512] -> d_out
    proj_gemm_kernel<<<dim3(C_DIM / 128, M_ROWS / 128), 128, SMEM_BYTES>>>(proj_b, out);
}

// round 14
// speedup vs baseline: 1.2187x; 1.2187x over previous
#include <cuda_runtime.h>
#include <cuda_fp16.h>
#include <math.h>
#include <stdint.h>

// ---------------------------------------------------------------------------
// Problem constants
// ---------------------------------------------------------------------------
#define BWIN    2048
#define N_TOK   49
#define C_DIM   512
#define N_HEADS 16
#define HD      32
#define QKV_N   1536
#define M_ROWS  (BWIN * N_TOK)     // 100352 = 784 * 128
#define NN      (N_TOK * N_TOK)    // 2401
#define NWMASK  64

// ---------------------------------------------------------------------------
// Scratch (static device globals) — all operand splits are fp16 hi/lo
// ---------------------------------------------------------------------------
__device__ float g_qkv[(size_t)M_ROWS * QKV_N];      // fp32 qkv
__device__ __half g_xh[(size_t)M_ROWS * C_DIM];      // x split hi   [M,K]
__device__ __half g_xl[(size_t)M_ROWS * C_DIM];      // x split lo
__device__ __half g_aoh[(size_t)M_ROWS * C_DIM];     // attn out hi  [M,K]
__device__ __half g_aol[(size_t)M_ROWS * C_DIM];     // attn out lo
__device__ __half g_qwh[C_DIM * QKV_N];              // qkv_w hi  [K,N]
__device__ __half g_qwl[C_DIM * QKV_N];              // qkv_w lo
__device__ __half g_pwh[C_DIM * C_DIM];              // proj_w hi [K,N]
__device__ __half g_pwl[C_DIM * C_DIM];              // proj_w lo
__device__ float g_pb [N_HEADS * NN];
__device__ float g_qkvbias[QKV_N];

// ---------------------------------------------------------------------------
// Helpers
// ---------------------------------------------------------------------------
__device__ __forceinline__ uint32_t pack2(__half a, __half b) {
    __half2 v = __halves2half2(a, b);
    return *(uint32_t*)&v;
}
__device__ __forceinline__ void split1(float v, __half& h, __half& l) {
    h = __float2half_rn(v);
    l = __float2half_rn(v - __half2float(h));
}

__device__ __forceinline__ void mma_f16(float d[4],
                                        const uint32_t a[4],
                                        const uint32_t b[2]) {
    asm volatile(
        "mma.sync.aligned.m16n8k16.row.col.f32.f16.f16.f32 "
        "{%0,%1,%2,%3}, {%4,%5,%6,%7}, {%8,%9}, {%0,%1,%2,%3};\n"
        : "+f"(d[0]), "+f"(d[1]), "+f"(d[2]), "+f"(d[3])
        : "r"(a[0]), "r"(a[1]), "r"(a[2]), "r"(a[3]), "r"(b[0]), "r"(b[1]));
}
__device__ __forceinline__ void ldsm_x4(uint32_t r[4], uint32_t addr) {
    asm volatile("ldmatrix.sync.aligned.m8n8.x4.shared.b16 {%0,%1,%2,%3}, [%4];\n"
                 : "=r"(r[0]), "=r"(r[1]), "=r"(r[2]), "=r"(r[3]) : "r"(addr));
}
__device__ __forceinline__ void ldsm_x2t(uint32_t r[2], uint32_t addr) {
    asm volatile("ldmatrix.sync.aligned.m8n8.x2.trans.shared.b16 {%0,%1}, [%2];\n"
                 : "=r"(r[0]), "=r"(r[1]) : "r"(addr));
}
__device__ __forceinline__ void cp16(uint32_t dst, const void* src) {
    asm volatile("cp.async.cg.shared.global [%0], [%1], 16;\n" :: "r"(dst), "l"(src));
}
__device__ __forceinline__ void cp_commit() { asm volatile("cp.async.commit_group;\n"); }
__device__ __forceinline__ void cp_wait1()  { asm volatile("cp.async.wait_group 1;\n" ::: "memory"); }

// ---------------------------------------------------------------------------
// Split kernel: fp32 -> fp16 hi/lo (vectorized x4)
// ---------------------------------------------------------------------------
__global__ void split_kernel(const float* __restrict__ src,
                             __half* __restrict__ dh,
                             __half* __restrict__ dl, int n4) {
    int i = blockIdx.x * blockDim.x + threadIdx.x;
    if (i >= n4) return;
    float4 v = ((const float4*)src)[i];
    __half hx, lx, hy, ly, hz, lz, hw, lw;
    split1(v.x, hx, lx); split1(v.y, hy, ly);
    split1(v.z, hz, lz); split1(v.w, hw, lw);
    uint2 ph, pl;
    ph.x = pack2(hx, hy); ph.y = pack2(hz, hw);
    pl.x = pack2(lx, ly); pl.y = pack2(lz, lw);
    ((uint2*)dh)[i] = ph;
    ((uint2*)dl)[i] = pl;
}

// ---------------------------------------------------------------------------
// Kernel 1: RPE table MLP + bias gather + qkv bias vector
// ---------------------------------------------------------------------------
__device__ __forceinline__ float coord_feat(int x) {
    float xs = (float)x * (8.0f / 121.0f);
    float v = log1pf(fabsf(xs)) * 0.48089834696298783f; // 1/ln(8)
    return copysignf(v, xs);
}

__global__ void setup_kernel(const float* __restrict__ rpe_w1,
                             const float* __restrict__ rpe_b1,
                             const float* __restrict__ rpe_w2,
                             const float* __restrict__ q_bias,
                             const float* __restrict__ v_bias) {
    __shared__ float sbt[169 * N_HEADS];
    const int tid = threadIdx.x; // 256 threads

    if (tid < 169) {
        int a = tid / 13, b = tid % 13;
        float c0 = coord_feat(b - 6);
        float c1 = coord_feat(a - 6);
        float acc[N_HEADS];
        #pragma unroll
        for (int t = 0; t < N_HEADS; t++) acc[t] = 0.f;
        for (int j = 0; j < 512; j++) {
            float h1 = fmaf(c0, rpe_w1[j], fmaf(c1, rpe_w1[512 + j], rpe_b1[j]));
            h1 = fmaxf(h1, 0.f);
            const float* w2 = rpe_w2 + j * N_HEADS;
            #pragma unroll
            for (int t = 0; t < N_HEADS; t++) acc[t] = fmaf(h1, w2[t], acc[t]);
        }
        #pragma unroll
        for (int t = 0; t < N_HEADS; t++) sbt[tid * N_HEADS + t] = acc[t];
    }

    for (int c = tid; c < QKV_N; c += 256) {
        float v = 0.f;
        if (c < 512)        v = q_bias[c];
        else if (c >= 1024) v = v_bias[c - 1024];
        g_qkvbias[c] = v;
    }
    __syncthreads();

    for (int idx = tid; idx < N_HEADS * NN; idx += 256) {
        int h   = idx / NN;
        int rem = idx % NN;
        int n = rem / N_TOK, m = rem % N_TOK;
        int di = (n / 7) - (m / 7);
        int dj = (n % 7) - (m % 7);
        int r = (dj + 6) * 13 + (di + 6);
        float bt = sbt[r * N_HEADS + h];
        g_pb[idx] = 16.f / (1.f + expf(-bt));
    }
}

// ---------------------------------------------------------------------------
// Pipelined split-fp16 tensor-core GEMM (R11 structure: 2-stage, 4 warps,
// 64x64 warp tiles). `vstart`: block columns bn < vstart use 3-term
// (hi*hi + hi*lo + lo*hi); bn >= vstart use single-term fp16 (hi*hi only,
// lo tiles neither loaded nor read).
// ---------------------------------------------------------------------------
#define SA_STR 40
#define SB_STR 136
#define ASIZE (128 * SA_STR)
#define BSIZE (32 * SB_STR)
#define SMEM_BYTES ((2 * (2 * ASIZE + 2 * BSIZE)) * 2)  // 75776 B

__device__ __forceinline__ void gemm_issue(
    int it, int buf, int iters, int tid, int terms,
    const __half* Ah, const __half* Al,
    const __half* Bh, const __half* Bl,
    size_t Abase, int nblk, int N, int K,
    uint32_t sAh32, uint32_t sAl32, uint32_t sBh32, uint32_t sBl32)
{
    if (it < iters) {
        const int k0 = it * 32;
        const uint32_t aoff = (uint32_t)buf * (ASIZE * 2);
        const uint32_t boff = (uint32_t)buf * (BSIZE * 2);
        #pragma unroll
        for (int p = 0; p < 4; p++) {
            int c = tid + p * 128;
            int row = c >> 2, seg = (c & 3) * 8;
            size_t go = Abase + (size_t)row * K + k0 + seg;
            uint32_t ds = (uint32_t)(row * SA_STR + seg) * 2;
            cp16(sAh32 + aoff + ds, Ah + go);
            if (terms == 3) cp16(sAl32 + aoff + ds, Al + go);
        }
        #pragma unroll
        for (int p = 0; p < 4; p++) {
            int c = tid + p * 128;
            int row = c >> 4, seg = (c & 15) * 8;
            size_t go = (size_t)(k0 + row) * N + nblk + seg;
            uint32_t ds = (uint32_t)(row * SB_STR + seg) * 2;
            cp16(sBh32 + boff + ds, Bh + go);
            if (terms == 3) cp16(sBl32 + boff + ds, Bl + go);
        }
    }
    cp_commit();
}

__device__ __forceinline__ void gemm_core(
    const __half* __restrict__ Ah, const __half* __restrict__ Al,
    const __half* __restrict__ Bh, const __half* __restrict__ Bl,
    const float* __restrict__ bias, float* __restrict__ C, int N, int K,
    int vstart)
{
    extern __shared__ __half smem[];
    __half* sAh = smem;
    __half* sAl = sAh + 2 * ASIZE;
    __half* sBh = sAl + 2 * ASIZE;
    __half* sBl = sBh + 2 * BSIZE;

    const int tid  = threadIdx.x;          // 128 threads
    const int bm   = blockIdx.y, bn = blockIdx.x;
    const int terms = (bn < vstart) ? 3 : 1;
    const int lane = tid & 31;
    const int w    = tid >> 5;              // 0..3
    const int wm   = (w >> 1) * 64;
    const int wn   = (w & 1) * 64;
    const int l15  = lane & 15;
    const int lhi8 = (lane >> 4) * 8;

    const size_t Abase = (size_t)bm * 128 * K;
    const int nblk = bn * 128;

    const uint32_t sAh32 = (uint32_t)__cvta_generic_to_shared(sAh);
    const uint32_t sAl32 = (uint32_t)__cvta_generic_to_shared(sAl);
    const uint32_t sBh32 = (uint32_t)__cvta_generic_to_shared(sBh);
    const uint32_t sBl32 = (uint32_t)__cvta_generic_to_shared(sBl);

    float acc[4][8][4];
    #pragma unroll
    for (int mi = 0; mi < 4; mi++)
        #pragma unroll
        for (int ni = 0; ni < 8; ni++)
            #pragma unroll
            for (int r = 0; r < 4; r++) acc[mi][ni][r] = 0.f;

    const int iters = K / 32;
    gemm_issue(0, 0, iters, tid, terms, Ah, Al, Bh, Bl, Abase, nblk, N, K,
               sAh32, sAl32, sBh32, sBl32);
    gemm_issue(1, 1, iters, tid, terms, Ah, Al, Bh, Bl, Abase, nblk, N, K,
               sAh32, sAl32, sBh32, sBl32);

    for (int it = 0; it < iters; it++) {
        const int buf = it & 1;
        cp_wait1();
        __syncthreads();

        const uint32_t aoff = (uint32_t)buf * (ASIZE * 2);
        const uint32_t boff = (uint32_t)buf * (BSIZE * 2);

        if (terms == 3) {
            #pragma unroll
            for (int ks = 0; ks < 32; ks += 16) {
                uint32_t bh[8][2], bl[8][2];
                #pragma unroll
                for (int ni = 0; ni < 8; ni++) {
                    uint32_t ds = (uint32_t)((ks + l15) * SB_STR + wn + ni * 8) * 2;
                    ldsm_x2t(bh[ni], sBh32 + boff + ds);
                    ldsm_x2t(bl[ni], sBl32 + boff + ds);
                }
                #pragma unroll
                for (int mi = 0; mi < 4; mi++) {
                    uint32_t ds = (uint32_t)((wm + mi * 16 + l15) * SA_STR + ks + lhi8) * 2;
                    uint32_t ah[4], al[4];
                    ldsm_x4(ah, sAh32 + aoff + ds);
                    ldsm_x4(al, sAl32 + aoff + ds);
                    #pragma unroll
                    for (int ni = 0; ni < 8; ni++) {
                        mma_f16(acc[mi][ni], ah, bh[ni]);
                        mma_f16(acc[mi][ni], ah, bl[ni]);
                        mma_f16(acc[mi][ni], al, bh[ni]);
                    }
                }
            }
        } else {
            #pragma unroll
            for (int ks = 0; ks < 32; ks += 16) {
                uint32_t bh[8][2];
                #pragma unroll
                for (int ni = 0; ni < 8; ni++) {
                    uint32_t ds = (uint32_t)((ks + l15) * SB_STR + wn + ni * 8) * 2;
                    ldsm_x2t(bh[ni], sBh32 + boff + ds);
                }
                #pragma unroll
                for (int mi = 0; mi < 4; mi++) {
                    uint32_t ds = (uint32_t)((wm + mi * 16 + l15) * SA_STR + ks + lhi8) * 2;
                    uint32_t ah[4];
                    ldsm_x4(ah, sAh32 + aoff + ds);
                    #pragma unroll
                    for (int ni = 0; ni < 8; ni++)
                        mma_f16(acc[mi][ni], ah, bh[ni]);
                }
            }
        }
        __syncthreads();
        gemm_issue(it + 2, buf, iters, tid, terms, Ah, Al, Bh, Bl, Abase, nblk, N, K,
                   sAh32, sAl32, sBh32, sBl32);
    }

    const int g  = lane >> 2;
    const int t2 = (lane & 3) * 2;
    #pragma unroll
    for (int mi = 0; mi < 4; mi++) {
        int row = bm * 128 + wm + mi * 16 + g;
        #pragma unroll
        for (int ni = 0; ni < 8; ni++) {
            int col = bn * 128 + wn + ni * 8 + t2;
            float b0 = bias[col], b1 = bias[col + 1];
            float2 o0 = make_float2(acc[mi][ni][0] + b0, acc[mi][ni][1] + b1);
            float2 o1 = make_float2(acc[mi][ni][2] + b0, acc[mi][ni][3] + b1);
            *(float2*)(C + (size_t)row * N + col)       = o0;
            *(float2*)(C + (size_t)(row + 8) * N + col) = o1;
        }
    }
}

__global__ void __launch_bounds__(128, 2)
qkv_gemm_kernel() {
    // N-tiles 0..7 are q,k (3-term); tiles 8..11 are v (1-term fp16)
    gemm_core(g_xh, g_xl, g_qwh, g_qwl, g_qkvbias, g_qkv, QKV_N, C_DIM, 8);
}

__global__ void __launch_bounds__(128, 2)
proj_gemm_kernel(const float* __restrict__ proj_b, float* __restrict__ out) {
    // final projection: 1-term fp16 everywhere (error lands unamplified)
    gemm_core(g_aoh, g_aol, g_pwh, g_pwl, proj_b, out, C_DIM, C_DIM, 0);
}

// ---------------------------------------------------------------------------
// Kernel 3: tensor-core attention per (window, head) — R10 structure,
// fp16 splits (hi has 11 bits: sensitive QK path gets MORE precise).
// ---------------------------------------------------------------------------
#define ATT_QH  0
#define ATT_QL  5120
#define ATT_KTH 10240
#define ATT_KTL 14848
#define ATT_VH  19456
#define ATT_VL  24576
#define ATT_SS  29696
#define ATT_TOT (29696 + 64 * 66 * 4)   // 46592 B
#define ATT_PH  0
#define ATT_PL  9216

__global__ void __launch_bounds__(256, 2)
attn_kernel(const float* __restrict__ mask, const float* __restrict__ logit_scale) {
    const int b = blockIdx.x >> 4;
    const int h = blockIdx.x & 15;
    const int tid  = threadIdx.x;
    const int lane = tid & 31;
    const int w    = tid >> 5;

    __shared__ __align__(16) char sm[ATT_TOT];
    __half* sQh  = (__half*)(sm + ATT_QH);
    __half* sQl  = (__half*)(sm + ATT_QL);
    __half* sKth = (__half*)(sm + ATT_KTH);
    __half* sKtl = (__half*)(sm + ATT_KTL);
    __half* sVh  = (__half*)(sm + ATT_VH);
    __half* sVl  = (__half*)(sm + ATT_VL);
    __half* sPh  = (__half*)(sm + ATT_PH);
    __half* sPl  = (__half*)(sm + ATT_PL);
    float* sS = (float*)(sm + ATT_SS);
    const uint32_t smb = (uint32_t)__cvta_generic_to_shared(sm);

    // ---- Phase 1 ----
    const float* base = g_qkv + (size_t)b * N_TOK * QKV_N + h * HD;
    #pragma unroll
    for (int p = 0; p < 8; p++) {
        int idx = tid + p * 256;
        int r = idx >> 5, d = idx & 31;
        float qv = 0.f, kv = 0.f, vv = 0.f;
        if (r < N_TOK) {
            const float* pp = base + (size_t)r * QKV_N + d;
            qv = pp[0]; kv = pp[512]; vv = pp[1024];
        }
        sS[r * 66 + d]      = qv;
        sS[r * 66 + 32 + d] = kv;
        __half vh, vl;
        split1(vv, vh, vl);
        sVh[r * 40 + d] = vh;
        sVl[r * 40 + d] = vl;
    }
    __syncthreads();

    // ---- Phase 2 ----
    {
        const int r  = tid >> 2;
        const int qd = (tid & 3) * 8;
        float qv[8], kv[8];
        float sq = 0.f, sk = 0.f;
        #pragma unroll
        for (int j = 0; j < 8; j++) {
            qv[j] = sS[r * 66 + qd + j];
            kv[j] = sS[r * 66 + 32 + qd + j];
            sq = fmaf(qv[j], qv[j], sq);
            sk = fmaf(kv[j], kv[j], sk);
        }
        sq += __shfl_xor_sync(0xffffffff, sq, 1);
        sq += __shfl_xor_sync(0xffffffff, sq, 2);
        sk += __shfl_xor_sync(0xffffffff, sk, 1);
        sk += __shfl_xor_sync(0xffffffff, sk, 2);
        float hs  = __expf(fminf(logit_scale[h], 4.605170185988091f));
        float qsc = rsqrtf(fmaxf(sq, 1e-12f)) * hs;
        float ksc = rsqrtf(fmaxf(sk, 1e-12f));
        #pragma unroll
        for (int j = 0; j < 8; j += 2) {
            __half h0, l0, h1, l1;
            split1(qv[j] * qsc, h0, l0);
            split1(qv[j + 1] * qsc, h1, l1);
            *(uint32_t*)&sQh[r * 40 + qd + j] = pack2(h0, h1);
            *(uint32_t*)&sQl[r * 40 + qd + j] = pack2(l0, l1);
        }
        #pragma unroll
        for (int j = 0; j < 8; j++) {
            __half kh, kl;
            split1(kv[j] * ksc, kh, kl);
            sKth[(qd + j) * 72 + r] = kh;
            sKtl[(qd + j) * 72 + r] = kl;
        }
    }
    __syncthreads();

    // ---- Phase 3: S = Qn @ Kn^T ----
    {
        const int m0  = (w & 3) * 16;
        const int n0  = (w >> 2) * 32;
        const int l15 = lane & 15;
        const int lhi8 = (lane >> 4) * 8;
        float acc[4][4];
        #pragma unroll
        for (int ni = 0; ni < 4; ni++)
            #pragma unroll
            for (int r = 0; r < 4; r++) acc[ni][r] = 0.f;

        #pragma unroll
        for (int ks = 0; ks < 32; ks += 16) {
            uint32_t ah[4], al[4];
            uint32_t dsA = (uint32_t)(ATT_QH) + (uint32_t)((m0 + l15) * 40 + ks + lhi8) * 2;
            ldsm_x4(ah, smb + dsA);
            ldsm_x4(al, smb + dsA + (ATT_QL - ATT_QH));
            #pragma unroll
            for (int ni = 0; ni < 4; ni++) {
                uint32_t bh[2], bl[2];
                uint32_t dsB = (uint32_t)(ATT_KTH) + (uint32_t)((ks + l15) * 72 + n0 + ni * 8) * 2;
                ldsm_x2t(bh, smb + dsB);
                ldsm_x2t(bl, smb + dsB + (ATT_KTL - ATT_KTH));
                mma_f16(acc[ni], ah, bh);
                mma_f16(acc[ni], ah, bl);
                mma_f16(acc[ni], al, bh);
            }
        }
        const int g  = lane >> 2;
        const int t2 = (lane & 3) * 2;
        #pragma unroll
        for (int ni = 0; ni < 4; ni++) {
            int c = n0 + ni * 8 + t2;
            *(float2*)&sS[(m0 + g) * 66 + c]     = make_float2(acc[ni][0], acc[ni][1]);
            *(float2*)&sS[(m0 + 8 + g) * 66 + c] = make_float2(acc[ni][2], acc[ni][3]);
        }
    }
    __syncthreads();

    // ---- Phase 4: softmax, uniform across all 64 rows ----
    {
        const int r  = tid >> 2;
        const int c0 = (tid & 3) * 16;
        const int rr = (r < N_TOK) ? r : 0;
        const int ww = b & (NWMASK - 1);
        const float* pbr = g_pb + h * NN + rr * N_TOK;
        const float* mr  = mask + (size_t)ww * NN + rr * N_TOK;
        float vals[16];
        float mx = -1e30f;
        #pragma unroll
        for (int i = 0; i < 16; i++) {
            int m = c0 + i;
            float v = -1e30f;
            if (m < N_TOK) v = sS[r * 66 + m] + pbr[m] + mr[m];
            vals[i] = v;
            mx = fmaxf(mx, v);
        }
        mx = fmaxf(mx, __shfl_xor_sync(0xffffffff, mx, 1));
        mx = fmaxf(mx, __shfl_xor_sync(0xffffffff, mx, 2));
        float sum = 0.f;
        #pragma unroll
        for (int i = 0; i < 16; i++) {
            float e = (c0 + i < N_TOK) ? __expf(vals[i] - mx) : 0.f;
            vals[i] = e;
            sum += e;
        }
        sum += __shfl_xor_sync(0xffffffff, sum, 1);
        sum += __shfl_xor_sync(0xffffffff, sum, 2);
        float inv = 1.f / sum;
        #pragma unroll
        for (int i = 0; i < 16; i += 2) {
            __half h0, l0, h1, l1;
            split1(vals[i] * inv, h0, l0);
            split1(vals[i + 1] * inv, h1, l1);
            *(uint32_t*)&sPh[r * 72 + c0 + i] = pack2(h0, h1);
            *(uint32_t*)&sPl[r * 72 + c0 + i] = pack2(l0, l1);
        }
    }
    __syncthreads();

    // ---- Phase 5: O = P @ V; split-store fp16 output ----
    {
        const int m0  = (w & 3) * 16;
        const int n0  = (w >> 2) * 16;
        const int l15 = lane & 15;
        const int lhi8 = (lane >> 4) * 8;
        float acc[2][4];
        #pragma unroll
        for (int ni = 0; ni < 2; ni++)
            #pragma unroll
            for (int r = 0; r < 4; r++) acc[ni][r] = 0.f;

        #pragma unroll
        for (int ks = 0; ks < 64; ks += 16) {
            uint32_t ah[4], al[4];
            uint32_t dsA = (uint32_t)(ATT_PH) + (uint32_t)((m0 + l15) * 72 + ks + lhi8) * 2;
            ldsm_x4(ah, smb + dsA);
            ldsm_x4(al, smb + dsA + (ATT_PL - ATT_PH));
            #pragma unroll
            for (int ni = 0; ni < 2; ni++) {
                uint32_t bh[2], bl[2];
                uint32_t dsB = (uint32_t)(ATT_VH) + (uint32_t)((ks + l15) * 40 + n0 + ni * 8) * 2;
                ldsm_x2t(bh, smb + dsB);
                ldsm_x2t(bl, smb + dsB + (ATT_VL - ATT_VH));
                mma_f16(acc[ni], ah, bh);
                mma_f16(acc[ni], ah, bl);
                mma_f16(acc[ni], al, bh);
            }
        }
        const int g  = lane >> 2;
        const int t2 = (lane & 3) * 2;
        #pragma unroll
        for (int ni = 0; ni < 2; ni++) {
            int col  = h * HD + n0 + ni * 8 + t2;
            int row0 = m0 + g, row1 = m0 + 8 + g;
            if (row0 < N_TOK) {
                size_t o = ((size_t)b * N_TOK + row0) * C_DIM + col;
                __half h0, l0, h1, l1;
                split1(acc[ni][0], h0, l0);
                split1(acc[ni][1], h1, l1);
                *(uint32_t*)(g_aoh + o) = pack2(h0, h1);
                *(uint32_t*)(g_aol + o) = pack2(l0, l1);
            }
            if (row1 < N_TOK) {
                size_t o = ((size_t)b * N_TOK + row1) * C_DIM + col;
                __half h0, l0, h1, l1;
                split1(acc[ni][2], h0, l0);
                split1(acc[ni][3], h1, l1);
                *(uint32_t*)(g_aoh + o) = pack2(h0, h1);
                *(uint32_t*)(g_aol + o) = pack2(l0, l1);
            }
        }
    }
}

// ---------------------------------------------------------------------------
// Launch
// ---------------------------------------------------------------------------
extern "C" void kernel_launch(void* const* d_in, const int* in_sizes, int n_in,
                              void* d_out, int out_size) {
    const float* x           = (const float*)d_in[0];
    const float* mask        = (const float*)d_in[1];
    const float* qkv_w       = (const float*)d_in[2];
    const float* q_bias      = (const float*)d_in[3];
    const float* v_bias      = (const float*)d_in[4];
    const float* logit_scale = (const float*)d_in[5];
    const float* rpe_w1      = (const float*)d_in[6];
    const float* rpe_b1      = (const float*)d_in[7];
    const float* rpe_w2      = (const float*)d_in[8];
    const float* proj_w      = (const float*)d_in[9];
    const float* proj_b      = (const float*)d_in[10];
    float* out = (float*)d_out;

    cudaFuncSetAttribute(qkv_gemm_kernel,
                         cudaFuncAttributeMaxDynamicSharedMemorySize, SMEM_BYTES);
    cudaFuncSetAttribute(proj_gemm_kernel,
                         cudaFuncAttributeMaxDynamicSharedMemorySize, SMEM_BYTES);

    __half *xh, *xl, *qwh, *qwl, *pwh, *pwl;
    cudaGetSymbolAddress((void**)&xh,  g_xh);
    cudaGetSymbolAddress((void**)&xl,  g_xl);
    cudaGetSymbolAddress((void**)&qwh, g_qwh);
    cudaGetSymbolAddress((void**)&qwl, g_qwl);
    cudaGetSymbolAddress((void**)&pwh, g_pwh);
    cudaGetSymbolAddress((void**)&pwl, g_pwl);

    setup_kernel<<<1, 256>>>(rpe_w1, rpe_b1, rpe_w2, q_bias, v_bias);

    {
        int n4 = M_ROWS * C_DIM / 4;
        split_kernel<<<(n4 + 255) / 256, 256>>>(x, xh, xl, n4);
    }
    {
        int n4 = C_DIM * QKV_N / 4;
        split_kernel<<<(n4 + 255) / 256, 256>>>(qkv_w, qwh, qwl, n4);
    }
    {
        int n4 = C_DIM * C_DIM / 4;
        split_kernel<<<(n4 + 255) / 256, 256>>>(proj_w, pwh, pwl, n4);
    }

    // QKV: [100352,512] @ [512,1536]
    qkv_gemm_kernel<<<dim3(QKV_N / 128, M_ROWS / 128), 128, SMEM_BYTES>>>();

    attn_kernel<<<BWIN * N_HEADS, 256>>>(mask, logit_scale);

    // proj: [100352,512] @ [512,512] -> d_out
    proj_gemm_kernel<<<dim3(C_DIM / 128, M_ROWS / 128), 128, SMEM_BYTES>>>(proj_b, out);
}